// round 10
// baseline (speedup 1.0000x reference)
#include <cuda_runtime.h>
#include <cstdint>

#define HEADS 4
#define CB    8192
#define D     64
#define M     8192            // B*N
#define DIM   256             // HEADS*D
#define QSIZE (M*DIM)
#define TM 128                // queries per block
#define TN 128                // codes per tile
#define NTILES (CB/TN)        // 64
#define NTHREADS 128          // tx = t&7 (8 code groups of 16), ty = t>>3 (16 query groups of 8)

// dynamic smem:
//   Xs:  [64 k][128 q] f32 (k-major)   32768 B
//   Et:  [64 k][128 c] f32 (k-major)   32768 B
//   y2s: [128] f32, inds: [128] int
#define SM_XS_BYTES  (D * TM * 4)
#define SM_ET_OFF    SM_XS_BYTES
#define SM_ET_BYTES  (D * TN * 4)
#define SM_Y2_OFF    (SM_ET_OFF + SM_ET_BYTES)
#define SM_INDS_OFF  (SM_Y2_OFF + TN * 4)
#define SMEM_BYTES   (SM_INDS_OFF + TM * 4)     // ~66.5 KB -> 2 blocks/SM

__device__ float g_y2[HEADS * CB];

// ---------------------------------------------------------------------------
__global__ void vq_y2_kernel(const float* __restrict__ embed) {
    int gw   = (blockIdx.x * blockDim.x + threadIdx.x) >> 5;
    int lane = threadIdx.x & 31;
    if (gw >= HEADS * CB) return;
    float2 v = reinterpret_cast<const float2*>(embed + (size_t)gw * D)[lane];
    float s = fmaf(v.x, v.x, v.y * v.y);
    #pragma unroll
    for (int o = 16; o; o >>= 1) s += __shfl_xor_sync(0xffffffffu, s, o);
    if (lane == 0) g_y2[gw] = s;
}

// full-rate packed fp32 FMA (only reachable via PTX)
__device__ __forceinline__ void ffma2(unsigned long long& acc,
                                      unsigned long long a,
                                      unsigned long long b) {
    asm("fma.rn.f32x2 %0, %1, %2, %0;" : "+l"(acc) : "l"(a), "l"(b));
}

// (v, v) packed into one 64-bit reg pair — ALU MOVs, no smem bytes
__device__ __forceinline__ unsigned long long dupf(float v) {
    unsigned long long r;
    asm("mov.b64 %0, {%1, %1};" : "=l"(r) : "f"(v));
    return r;
}

__device__ __forceinline__ void upd(float sc, int cg, float& m, int& id) {
    if (sc > m) { m = sc; id = cg; }
}

// ---------------------------------------------------------------------------
// grid=(M/128, HEADS)=256 blocks (one wave at 2 blocks/SM), block=128.
// Fragment: 8 queries x 16 codes / thread; acc packs adjacent code pairs.
// score(c) = x.e_c - 0.5*|e_c|^2  (argmax-equivalent to -sqrt distance)
// ---------------------------------------------------------------------------
__global__ __launch_bounds__(NTHREADS, 2)
void vq_main_kernel(const float* __restrict__ x, const float* __restrict__ embed,
                    float* __restrict__ out, int out_size) {
    extern __shared__ char smem[];
    float* Xs   = reinterpret_cast<float*>(smem);
    float* Et   = reinterpret_cast<float*>(smem + SM_ET_OFF);
    float* y2s  = reinterpret_cast<float*>(smem + SM_Y2_OFF);
    int*   inds = reinterpret_cast<int*>(smem + SM_INDS_OFF);

    const int h  = blockIdx.y;
    const int m0 = blockIdx.x * TM;
    const int t  = threadIdx.x;
    const int tx = t & 7;           // 16 codes: 16tx .. 16tx+15
    const int ty = t >> 3;          // 8 queries: 8ty .. 8ty+7

    const float* ebase = embed + (size_t)h * CB * D;
    const float* y2b   = g_y2 + h * CB;

    // ---- fill Xs once: Xs[k][q] = x[m0+q][h*64+k]  (thread owns q = t) ----
    {
        const int r = t;
        #pragma unroll
        for (int kq = 0; kq < 16; kq++) {
            float4 f = *reinterpret_cast<const float4*>(
                x + (size_t)(m0 + r) * DIM + h * D + kq * 4);
            Xs[(4 * kq + 0) * TM + r] = f.x;
            Xs[(4 * kq + 1) * TM + r] = f.y;
            Xs[(4 * kq + 2) * TM + r] = f.z;
            Xs[(4 * kq + 3) * TM + r] = f.w;
        }
    }

    float rmax[8];
    int   ridx[8];
    #pragma unroll
    for (int i = 0; i < 8; i++) { rmax[i] = -3.4e38f; ridx[i] = 0; }

    const float4* XsF4 = reinterpret_cast<const float4*>(Xs);   // 32 float4 / k-row
    const float4* EtF4 = reinterpret_cast<const float4*>(Et);   // 32 float4 / k-row

    for (int tile = 0; tile < NTILES; tile++) {
        const int n0 = tile * TN;
        __syncthreads();     // prior tile done reading Et (publishes Xs on iter 0)
        // ---- fill Et k-major: thread owns column c = t (0..127) ----
        {
            const int c = t;
            #pragma unroll
            for (int kq = 0; kq < 16; kq++) {
                float4 f = *reinterpret_cast<const float4*>(
                    ebase + (size_t)(n0 + c) * D + kq * 4);
                Et[(4 * kq + 0) * TN + c] = f.x;
                Et[(4 * kq + 1) * TN + c] = f.y;
                Et[(4 * kq + 2) * TN + c] = f.z;
                Et[(4 * kq + 3) * TN + c] = f.w;
            }
            y2s[c] = y2b[n0 + c];
        }
        __syncthreads();

        // ---- 8q x 16c fragment; acc[i][p] = scores of codes (16tx+2p, +2p+1) ----
        unsigned long long acc[8][8];
        #pragma unroll
        for (int i = 0; i < 8; i++)
            #pragma unroll
            for (int p = 0; p < 8; p++) acc[i][p] = 0ull;

        #pragma unroll 2
        for (int k = 0; k < D; k++) {
            // X: 2 LDS.128 (queries 8ty..8ty+7), 4 distinct addrs / warp
            float4 xa = XsF4[k * 32 + 2 * ty + 0];
            float4 xb = XsF4[k * 32 + 2 * ty + 1];
            // E: 4 LDS.128 (codes 16tx..16tx+15), 8x16B consecutive / warp
            float4 ea = EtF4[k * 32 + 4 * tx + 0];
            float4 eb = EtF4[k * 32 + 4 * tx + 1];
            float4 ec = EtF4[k * 32 + 4 * tx + 2];
            float4 ed = EtF4[k * 32 + 4 * tx + 3];
            ulonglong2 e0 = *reinterpret_cast<ulonglong2*>(&ea);
            ulonglong2 e1 = *reinterpret_cast<ulonglong2*>(&eb);
            ulonglong2 e2 = *reinterpret_cast<ulonglong2*>(&ec);
            ulonglong2 e3 = *reinterpret_cast<ulonglong2*>(&ed);

            float xs[8] = {xa.x, xa.y, xa.z, xa.w, xb.x, xb.y, xb.z, xb.w};
            #pragma unroll
            for (int i = 0; i < 8; i++) {
                unsigned long long xi = dupf(xs[i]);
                ffma2(acc[i][0], xi, e0.x); ffma2(acc[i][1], xi, e0.y);
                ffma2(acc[i][2], xi, e1.x); ffma2(acc[i][3], xi, e1.y);
                ffma2(acc[i][4], xi, e2.x); ffma2(acc[i][5], xi, e2.y);
                ffma2(acc[i][6], xi, e3.x); ffma2(acc[i][7], xi, e3.y);
            }
        }

        // ---- running argmax, codes ascending (first-index tie-break) ----
        float yv[16];
        *reinterpret_cast<float4*>(&yv[0])  = reinterpret_cast<const float4*>(y2s)[4 * tx + 0];
        *reinterpret_cast<float4*>(&yv[4])  = reinterpret_cast<const float4*>(y2s)[4 * tx + 1];
        *reinterpret_cast<float4*>(&yv[8])  = reinterpret_cast<const float4*>(y2s)[4 * tx + 2];
        *reinterpret_cast<float4*>(&yv[12]) = reinterpret_cast<const float4*>(y2s)[4 * tx + 3];
        const int cg = n0 + 16 * tx;
        #pragma unroll
        for (int i = 0; i < 8; i++) {
            #pragma unroll
            for (int p = 0; p < 8; p++) {
                unsigned long long a = acc[i][p];
                upd(__uint_as_float((unsigned)a)         - 0.5f * yv[2 * p],     cg + 2 * p,     rmax[i], ridx[i]);
                upd(__uint_as_float((unsigned)(a >> 32)) - 0.5f * yv[2 * p + 1], cg + 2 * p + 1, rmax[i], ridx[i]);
            }
        }
    }

    // ---- reduce over the 8 tx lanes (xor 4,2,1 stays in each octet) ----
    #pragma unroll
    for (int i = 0; i < 8; i++) {
        float v = rmax[i];
        int  id = ridx[i];
        #pragma unroll
        for (int o = 4; o; o >>= 1) {
            float ov = __shfl_xor_sync(0xffffffffu, v, o);
            int   oi = __shfl_xor_sync(0xffffffffu, id, o);
            if (ov > v || (ov == v && oi < id)) { v = ov; id = oi; }
        }
        if (tx == 0) inds[8 * ty + i] = id;
    }
    __syncthreads();

    // ---- indices output (float, layout b n h) ----
    if (out_size >= QSIZE + M * HEADS)
        out[QSIZE + (size_t)(m0 + t) * HEADS + h] = (float)inds[t];

    // ---- gather quantized codes (layout b n (h d)) ----
    #pragma unroll
    for (int s = 0; s < 16; s++) {
        int slot = t + s * NTHREADS;
        int r = slot >> 4, kq = slot & 15;
        int id = inds[r];
        float4 v = *reinterpret_cast<const float4*>(ebase + (size_t)id * D + kq * 4);
        *reinterpret_cast<float4*>(out + (size_t)(m0 + r) * DIM + h * D + kq * 4) = v;
    }
}

extern "C" void kernel_launch(void* const* d_in, const int* in_sizes, int n_in,
                              void* d_out, int out_size) {
    const float* x     = (const float*)d_in[0];   // [4,2048,256]
    const float* embed = (const float*)d_in[1];   // [4,8192,64]
    float* out = (float*)d_out;

    cudaFuncSetAttribute(vq_main_kernel,
                         cudaFuncAttributeMaxDynamicSharedMemorySize, SMEM_BYTES);

    vq_y2_kernel<<<(HEADS * CB) / 8, 256>>>(embed);

    dim3 grid(M / TM, HEADS);
    vq_main_kernel<<<grid, NTHREADS, SMEM_BYTES>>>(x, embed, out, out_size);
}

// round 11
// speedup vs baseline: 1.8568x; 1.8568x over previous
#include <cuda_runtime.h>
#include <cstdint>

#define HEADS 4
#define CB    8192
#define D     64
#define M     8192            // B*N
#define DIM   256
#define QSIZE (M*DIM)
#define TMQ   64              // queries per block
#define TNC   64              // codes per tile
#define NTILES (CB/TNC)       // 128
#define NTHREADS 256

// fragment-order hi/lo scratch (module globals; no runtime alloc)
// X: ablock = h*512 + (q/16); [ablock][chunk 8][lane 32][4]
// E: eblock = h*1024 + (c/8); [eblock][chunk 8][lane 32][2]
__device__ float gXhi[2097152];
__device__ float gXlo[2097152];
__device__ float gBhi[2097152];
__device__ float gBlo[2097152];
__device__ float g_y2[HEADS * CB];

// smem layout (bytes)
#define SM_AHI   0
#define SM_ALO   16384
#define SM_EHI   32768
#define SM_ELO   49152
#define SM_Y2    65536        // 64 f32
#define SM_SRED  65792        // 2*64 f32
#define SM_IRED  66304        // 2*64 int
#define SM_INDS  66816        // 64 int
#define SMEM_BYTES 67072

// ---------------------------------------------------------------------------
__device__ __forceinline__ uint32_t to_tf32(float f) {
    uint32_t r;
    asm("cvt.rna.tf32.f32 %0, %1;" : "=r"(r) : "f"(f));
    return r;
}

__device__ __forceinline__ void mma_tf32(float c[4], const uint32_t a[4],
                                         uint32_t b0, uint32_t b1) {
    asm volatile(
        "mma.sync.aligned.m16n8k8.row.col.f32.tf32.tf32.f32 "
        "{%0,%1,%2,%3}, {%4,%5,%6,%7}, {%8,%9}, {%0,%1,%2,%3};"
        : "+f"(c[0]), "+f"(c[1]), "+f"(c[2]), "+f"(c[3])
        : "r"(a[0]), "r"(a[1]), "r"(a[2]), "r"(a[3]), "r"(b0), "r"(b1));
}

// ---------------------------------------------------------------------------
__global__ void vq_y2_kernel(const float* __restrict__ embed) {
    int gw   = (blockIdx.x * blockDim.x + threadIdx.x) >> 5;
    int lane = threadIdx.x & 31;
    if (gw >= HEADS * CB) return;
    float2 v = reinterpret_cast<const float2*>(embed + (size_t)gw * D)[lane];
    float s = fmaf(v.x, v.x, v.y * v.y);
    #pragma unroll
    for (int o = 16; o; o >>= 1) s += __shfl_xor_sync(0xffffffffu, s, o);
    if (lane == 0) g_y2[gw] = s;
}

// ---------------------------------------------------------------------------
// X prep: one thread per (ablock, chunk, lane); writes float4 hi + lo in
// A-fragment order: a0=A[g][tg], a1=A[g+8][tg], a2=A[g][tg+4], a3=A[g+8][tg+4]
// ---------------------------------------------------------------------------
__global__ void vq_xprep_kernel(const float* __restrict__ x) {
    int tid = blockIdx.x * blockDim.x + threadIdx.x;   // < 524288
    int lane = tid & 31, chunk = (tid >> 5) & 7, ab = tid >> 8;
    int h = ab >> 9, mbg = ab & 511;
    int g = lane >> 2, tg = lane & 3;
    size_t base = (size_t)(16 * mbg + g) * DIM + h * D + 8 * chunk;
    float a0 = x[base + tg];
    float a1 = x[base + 8 * DIM + tg];
    float a2 = x[base + tg + 4];
    float a3 = x[base + 8 * DIM + tg + 4];
    uint32_t h0 = to_tf32(a0), h1 = to_tf32(a1), h2 = to_tf32(a2), h3 = to_tf32(a3);
    float f0 = __uint_as_float(h0), f1 = __uint_as_float(h1);
    float f2 = __uint_as_float(h2), f3 = __uint_as_float(h3);
    size_t o = (size_t)tid * 4;
    *reinterpret_cast<float4*>(gXhi + o) = make_float4(f0, f1, f2, f3);
    *reinterpret_cast<float4*>(gXlo + o) = make_float4(
        __uint_as_float(to_tf32(a0 - f0)), __uint_as_float(to_tf32(a1 - f1)),
        __uint_as_float(to_tf32(a2 - f2)), __uint_as_float(to_tf32(a3 - f3)));
}

// ---------------------------------------------------------------------------
// E prep: one thread per (eblock, chunk, lane); B-fragment order:
// b0 = B[k=tg][n=g] = e[n][k], b1 = e[n][k+4]
// ---------------------------------------------------------------------------
__global__ void vq_eprep_kernel(const float* __restrict__ embed) {
    int tid = blockIdx.x * blockDim.x + threadIdx.x;   // < 1048576
    int lane = tid & 31, chunk = (tid >> 5) & 7, eb = tid >> 8;
    int h = eb >> 10, nbg = eb & 1023;
    int g = lane >> 2, tg = lane & 3;
    size_t base = ((size_t)h * CB + 8 * nbg + g) * D + 8 * chunk + tg;
    float b0 = embed[base];
    float b1 = embed[base + 4];
    uint32_t h0 = to_tf32(b0), h1 = to_tf32(b1);
    float f0 = __uint_as_float(h0), f1 = __uint_as_float(h1);
    size_t o = (size_t)tid * 2;
    *reinterpret_cast<float2*>(gBhi + o) = make_float2(f0, f1);
    *reinterpret_cast<float2*>(gBlo + o) = make_float2(
        __uint_as_float(to_tf32(b0 - f0)), __uint_as_float(to_tf32(b1 - f1)));
}

// ---------------------------------------------------------------------------
// Main: grid (M/64, HEADS), 256 thr = 8 warps (mb = w>>1, nb = w&1).
// Warp: m16 block mb vs 32 codes (4 n8-subtiles).  3xTF32 per subtile.
// score(c) = x.e_c - 0.5*|e_c|^2 ; argmax with first-index tie-break.
// ---------------------------------------------------------------------------
__global__ __launch_bounds__(NTHREADS, 2)
void vq_main_kernel(const float* __restrict__ embed,
                    float* __restrict__ out, int out_size) {
    extern __shared__ char smem[];
    float* Ahi  = reinterpret_cast<float*>(smem + SM_AHI);
    float* Alo  = reinterpret_cast<float*>(smem + SM_ALO);
    float* Ehi  = reinterpret_cast<float*>(smem + SM_EHI);
    float* Elo  = reinterpret_cast<float*>(smem + SM_ELO);
    float* y2s  = reinterpret_cast<float*>(smem + SM_Y2);
    float* sred = reinterpret_cast<float*>(smem + SM_SRED);
    int*   ired = reinterpret_cast<int*>(smem + SM_IRED);
    int*   inds = reinterpret_cast<int*>(smem + SM_INDS);

    const int h = blockIdx.y, bm = blockIdx.x;
    const int t = threadIdx.x, lane = t & 31, w = t >> 5;
    const int mb = w >> 1, nb = w & 1;
    const int g = lane >> 2, tg = lane & 3;

    // ---- A fill (once): 4 contiguous ablocks = 4096 f32 each of hi/lo ----
    {
        const float4* xs = reinterpret_cast<const float4*>(
            gXhi + (size_t)(h * 512 + bm * 4) * 1024);
        const float4* xl = reinterpret_cast<const float4*>(
            gXlo + (size_t)(h * 512 + bm * 4) * 1024);
        #pragma unroll
        for (int i = 0; i < 4; i++) {
            reinterpret_cast<float4*>(Ahi)[t + i * 256] = xs[t + i * 256];
            reinterpret_cast<float4*>(Alo)[t + i * 256] = xl[t + i * 256];
        }
    }

    const float* y2b = g_y2 + h * CB;
    float rm0 = -3.4e38f, rm1 = -3.4e38f;
    int   ri0 = 0,        ri1 = 0;

    for (int tile = 0; tile < NTILES; tile++) {
        __syncthreads();     // prior tile done with Ehi/Elo/y2s (A published on iter 0)
        // ---- E fill: 8 contiguous eblocks = 4096 f32 each of hi/lo ----
        {
            const float4* es = reinterpret_cast<const float4*>(
                gBhi + (size_t)(h * 1024 + tile * 8) * 512);
            const float4* el = reinterpret_cast<const float4*>(
                gBlo + (size_t)(h * 1024 + tile * 8) * 512);
            #pragma unroll
            for (int i = 0; i < 4; i++) {
                reinterpret_cast<float4*>(Ehi)[t + i * 256] = es[t + i * 256];
                reinterpret_cast<float4*>(Elo)[t + i * 256] = el[t + i * 256];
            }
            if (t < TNC) y2s[t] = y2b[tile * TNC + t];
        }
        __syncthreads();

        float c[4][4];
        #pragma unroll
        for (int nt = 0; nt < 4; nt++)
            #pragma unroll
            for (int j = 0; j < 4; j++) c[nt][j] = 0.0f;

        #pragma unroll
        for (int chunk = 0; chunk < 8; chunk++) {
            float4 ah4 = reinterpret_cast<const float4*>(Ahi)[(mb * 8 + chunk) * 32 + lane];
            float4 al4 = reinterpret_cast<const float4*>(Alo)[(mb * 8 + chunk) * 32 + lane];
            uint32_t ah[4] = {__float_as_uint(ah4.x), __float_as_uint(ah4.y),
                              __float_as_uint(ah4.z), __float_as_uint(ah4.w)};
            uint32_t al[4] = {__float_as_uint(al4.x), __float_as_uint(al4.y),
                              __float_as_uint(al4.z), __float_as_uint(al4.w)};
            #pragma unroll
            for (int nt = 0; nt < 4; nt++) {
                int nblk = nb * 4 + nt;
                float2 bh = reinterpret_cast<const float2*>(Ehi)[(nblk * 8 + chunk) * 32 + lane];
                float2 bl = reinterpret_cast<const float2*>(Elo)[(nblk * 8 + chunk) * 32 + lane];
                uint32_t bh0 = __float_as_uint(bh.x), bh1 = __float_as_uint(bh.y);
                uint32_t bl0 = __float_as_uint(bl.x), bl1 = __float_as_uint(bl.y);
                mma_tf32(c[nt], ah, bh0, bh1);   // hi*hi
                mma_tf32(c[nt], ah, bl0, bl1);   // hi*lo
                mma_tf32(c[nt], al, bh0, bh1);   // lo*hi
            }
        }

        // ---- epilogue: running argmax (ascending codes, strict >) ----
        #pragma unroll
        for (int nt = 0; nt < 4; nt++) {
            int loc  = nb * 32 + nt * 8 + 2 * tg;
            int cbase = tile * TNC + loc;
            float y0 = y2s[loc], y1 = y2s[loc + 1];
            float s;
            s = c[nt][0] - 0.5f * y0; if (s > rm0) { rm0 = s; ri0 = cbase; }
            s = c[nt][1] - 0.5f * y1; if (s > rm0) { rm0 = s; ri0 = cbase + 1; }
            s = c[nt][2] - 0.5f * y0; if (s > rm1) { rm1 = s; ri1 = cbase; }
            s = c[nt][3] - 0.5f * y1; if (s > rm1) { rm1 = s; ri1 = cbase + 1; }
        }
    }

    // ---- reduce over the 4 tg lanes (xor 1,2 stays inside quad) ----
    #pragma unroll
    for (int o = 1; o <= 2; o <<= 1) {
        float ov; int oi;
        ov = __shfl_xor_sync(0xffffffffu, rm0, o);
        oi = __shfl_xor_sync(0xffffffffu, ri0, o);
        if (ov > rm0 || (ov == rm0 && oi < ri0)) { rm0 = ov; ri0 = oi; }
        ov = __shfl_xor_sync(0xffffffffu, rm1, o);
        oi = __shfl_xor_sync(0xffffffffu, ri1, o);
        if (ov > rm1 || (ov == rm1 && oi < ri1)) { rm1 = ov; ri1 = oi; }
    }
    if (tg == 0) {
        int r = mb * 16 + g;
        sred[nb * 64 + r]     = rm0;  ired[nb * 64 + r]     = ri0;
        sred[nb * 64 + r + 8] = rm1;  ired[nb * 64 + r + 8] = ri1;
    }
    __syncthreads();

    if (t < TMQ) {
        float s0 = sred[t], s1 = sred[64 + t];
        int   i0 = ired[t], i1 = ired[64 + t];
        int id = (s1 > s0 || (s1 == s0 && i1 < i0)) ? i1 : i0;
        inds[t] = id;
        if (out_size >= QSIZE + M * HEADS)
            out[QSIZE + (size_t)(bm * TMQ + t) * HEADS + h] = (float)id;
    }
    __syncthreads();

    // ---- gather quantized codes (layout b n (h d)) ----
    const float* ebase = embed + (size_t)h * CB * D;
    #pragma unroll
    for (int s = 0; s < 4; s++) {
        int slot = t + s * NTHREADS;
        int r = slot >> 4, kq = slot & 15;
        int id = inds[r];
        float4 v = *reinterpret_cast<const float4*>(ebase + (size_t)id * D + kq * 4);
        *reinterpret_cast<float4*>(out + (size_t)(bm * TMQ + r) * DIM + h * D + kq * 4) = v;
    }
}

extern "C" void kernel_launch(void* const* d_in, const int* in_sizes, int n_in,
                              void* d_out, int out_size) {
    const float* x     = (const float*)d_in[0];   // [4,2048,256]
    const float* embed = (const float*)d_in[1];   // [4,8192,64]
    float* out = (float*)d_out;

    cudaFuncSetAttribute(vq_main_kernel,
                         cudaFuncAttributeMaxDynamicSharedMemorySize, SMEM_BYTES);

    vq_y2_kernel<<<(HEADS * CB) / 8, 256>>>(embed);
    vq_xprep_kernel<<<2048, 256>>>(x);
    vq_eprep_kernel<<<4096, 256>>>(embed);

    dim3 grid(M / TMQ, HEADS);
    vq_main_kernel<<<grid, NTHREADS, SMEM_BYTES>>>(embed, out, out_size);
}

// round 12
// speedup vs baseline: 2.0785x; 1.1194x over previous
#include <cuda_runtime.h>
#include <cstdint>

#define HEADS 4
#define CB    8192
#define D     64
#define M     8192            // B*N
#define DIM   256
#define QSIZE (M*DIM)
#define TMQ   64              // queries per block
#define TNC   64              // codes per tile
#define NTILES (CB/TNC)       // 128
#define NTHREADS 256

// fragment-order scratch (module globals; no runtime alloc)
// X: ablock = h*512 + (q/16); [ablock][chunk 8][lane 32][4]  (hi and lo separate)
// B packed: eblock = h*1024 + (c/8); [eblock][chunk 8][lane 32][4] = (hi0,hi1,lo0,lo1)
__device__ float gXhi[2097152];
__device__ float gXlo[2097152];
__device__ float gBpk[4194304];
__device__ float g_y2[HEADS * CB];

// smem layout (bytes): Es 32768 | y2 256 | sred 512 | ired 512 | inds 256
#define SM_ES    0
#define SM_Y2    32768
#define SM_SRED  33024
#define SM_IRED  33536
#define SM_INDS  34048
#define SMEM_BYTES 34304

// ---------------------------------------------------------------------------
__device__ __forceinline__ uint32_t to_tf32(float f) {
    uint32_t r;
    asm("cvt.rna.tf32.f32 %0, %1;" : "=r"(r) : "f"(f));
    return r;
}

__device__ __forceinline__ void mma_tf32(float c[4], const uint32_t a[4],
                                         uint32_t b0, uint32_t b1) {
    asm volatile(
        "mma.sync.aligned.m16n8k8.row.col.f32.tf32.tf32.f32 "
        "{%0,%1,%2,%3}, {%4,%5,%6,%7}, {%8,%9}, {%0,%1,%2,%3};"
        : "+f"(c[0]), "+f"(c[1]), "+f"(c[2]), "+f"(c[3])
        : "r"(a[0]), "r"(a[1]), "r"(a[2]), "r"(a[3]), "r"(b0), "r"(b1));
}

// ---------------------------------------------------------------------------
__global__ void vq_y2_kernel(const float* __restrict__ embed) {
    int gw   = (blockIdx.x * blockDim.x + threadIdx.x) >> 5;
    int lane = threadIdx.x & 31;
    if (gw >= HEADS * CB) return;
    float2 v = reinterpret_cast<const float2*>(embed + (size_t)gw * D)[lane];
    float s = fmaf(v.x, v.x, v.y * v.y);
    #pragma unroll
    for (int o = 16; o; o >>= 1) s += __shfl_xor_sync(0xffffffffu, s, o);
    if (lane == 0) g_y2[gw] = s;
}

// ---------------------------------------------------------------------------
// X prep: A-fragment order: a0=A[g][tg], a1=A[g+8][tg], a2=A[g][tg+4], a3=A[g+8][tg+4]
// ---------------------------------------------------------------------------
__global__ void vq_xprep_kernel(const float* __restrict__ x) {
    int tid = blockIdx.x * blockDim.x + threadIdx.x;   // < 524288
    int lane = tid & 31, chunk = (tid >> 5) & 7, ab = tid >> 8;
    int h = ab >> 9, mbg = ab & 511;
    int g = lane >> 2, tg = lane & 3;
    size_t base = (size_t)(16 * mbg + g) * DIM + h * D + 8 * chunk;
    float a0 = x[base + tg];
    float a1 = x[base + 8 * DIM + tg];
    float a2 = x[base + tg + 4];
    float a3 = x[base + 8 * DIM + tg + 4];
    float f0 = __uint_as_float(to_tf32(a0)), f1 = __uint_as_float(to_tf32(a1));
    float f2 = __uint_as_float(to_tf32(a2)), f3 = __uint_as_float(to_tf32(a3));
    size_t o = (size_t)tid * 4;
    *reinterpret_cast<float4*>(gXhi + o) = make_float4(f0, f1, f2, f3);
    *reinterpret_cast<float4*>(gXlo + o) = make_float4(
        __uint_as_float(to_tf32(a0 - f0)), __uint_as_float(to_tf32(a1 - f1)),
        __uint_as_float(to_tf32(a2 - f2)), __uint_as_float(to_tf32(a3 - f3)));
}

// ---------------------------------------------------------------------------
// E prep: packed B fragments (hi0, hi1, lo0, lo1) per (eblock, chunk, lane).
// b0 = e[n=g][k=tg], b1 = e[n=g][k=tg+4]
// ---------------------------------------------------------------------------
__global__ void vq_eprep_kernel(const float* __restrict__ embed) {
    int tid = blockIdx.x * blockDim.x + threadIdx.x;   // < 1048576
    int lane = tid & 31, chunk = (tid >> 5) & 7, eb = tid >> 8;
    int h = eb >> 10, nbg = eb & 1023;
    int g = lane >> 2, tg = lane & 3;
    size_t base = ((size_t)h * CB + 8 * nbg + g) * D + 8 * chunk + tg;
    float b0 = embed[base];
    float b1 = embed[base + 4];
    float f0 = __uint_as_float(to_tf32(b0)), f1 = __uint_as_float(to_tf32(b1));
    *reinterpret_cast<float4*>(gBpk + (size_t)tid * 4) = make_float4(
        f0, f1,
        __uint_as_float(to_tf32(b0 - f0)), __uint_as_float(to_tf32(b1 - f1)));
}

// ---------------------------------------------------------------------------
// Main: grid (M/64, HEADS), 256 thr = 8 warps (mb = w>>1, nb = w&1).
// A fragments resident in registers (loaded once from global, frag order).
// Per chunk: 4 packed-B LDS.128 -> 12 MMAs. Split accumulators:
//   chh += Ahi*Bhi ; cxx += Ahi*Blo + Alo*Bhi  (8 indep chains / warp)
// score(c) = x.e_c - 0.5*|e_c|^2 ; argmax, first-index tie-break.
// ---------------------------------------------------------------------------
__global__ __launch_bounds__(NTHREADS, 2)
void vq_main_kernel(const float* __restrict__ embed,
                    float* __restrict__ out, int out_size) {
    extern __shared__ char smem[];
    float* Es   = reinterpret_cast<float*>(smem + SM_ES);
    float* y2s  = reinterpret_cast<float*>(smem + SM_Y2);
    float* sred = reinterpret_cast<float*>(smem + SM_SRED);
    int*   ired = reinterpret_cast<int*>(smem + SM_IRED);
    int*   inds = reinterpret_cast<int*>(smem + SM_INDS);

    const int h = blockIdx.y, bm = blockIdx.x;
    const int t = threadIdx.x, lane = t & 31, w = t >> 5;
    const int mb = w >> 1, nb = w & 1;
    const int g = lane >> 2, tg = lane & 3;

    // ---- A fragments -> registers (once). ablock = h*512 + bm*4 + mb ----
    uint32_t Ah[8][4], Al[8][4];
    {
        const float4* xh = reinterpret_cast<const float4*>(gXhi) +
                           (size_t)(h * 512 + bm * 4 + mb) * 256;
        const float4* xl = reinterpret_cast<const float4*>(gXlo) +
                           (size_t)(h * 512 + bm * 4 + mb) * 256;
        #pragma unroll
        for (int c = 0; c < 8; c++) {
            float4 vh = xh[c * 32 + lane];
            float4 vl = xl[c * 32 + lane];
            Ah[c][0] = __float_as_uint(vh.x); Ah[c][1] = __float_as_uint(vh.y);
            Ah[c][2] = __float_as_uint(vh.z); Ah[c][3] = __float_as_uint(vh.w);
            Al[c][0] = __float_as_uint(vl.x); Al[c][1] = __float_as_uint(vl.y);
            Al[c][2] = __float_as_uint(vl.z); Al[c][3] = __float_as_uint(vl.w);
        }
    }

    const float* y2b = g_y2 + h * CB;
    float rm0 = -3.4e38f, rm1 = -3.4e38f;
    int   ri0 = 0,        ri1 = 0;

    const float4* EsF4 = reinterpret_cast<const float4*>(Es);

    for (int tile = 0; tile < NTILES; tile++) {
        __syncthreads();     // prior tile done with Es/y2s
        // ---- E fill: 8 eblocks packed = 2048 float4 ----
        {
            const float4* ep = reinterpret_cast<const float4*>(gBpk) +
                               (size_t)(h * 1024 + tile * 8) * 256;
            #pragma unroll
            for (int i = 0; i < 8; i++)
                reinterpret_cast<float4*>(Es)[t + i * 256] = ep[t + i * 256];
            if (t < TNC) y2s[t] = y2b[tile * TNC + t];
        }
        __syncthreads();

        float chh[4][4], cxx[4][4];
        #pragma unroll
        for (int nt = 0; nt < 4; nt++)
            #pragma unroll
            for (int j = 0; j < 4; j++) { chh[nt][j] = 0.0f; cxx[nt][j] = 0.0f; }

        #pragma unroll
        for (int chunk = 0; chunk < 8; chunk++) {
            #pragma unroll
            for (int nt = 0; nt < 4; nt++) {
                int nblk = nb * 4 + nt;
                float4 bp = EsF4[(nblk * 8 + chunk) * 32 + lane];
                uint32_t bh0 = __float_as_uint(bp.x), bh1 = __float_as_uint(bp.y);
                uint32_t bl0 = __float_as_uint(bp.z), bl1 = __float_as_uint(bp.w);
                mma_tf32(chh[nt], Ah[chunk], bh0, bh1);   // hi*hi
                mma_tf32(cxx[nt], Ah[chunk], bl0, bl1);   // hi*lo
                mma_tf32(cxx[nt], Al[chunk], bh0, bh1);   // lo*hi
            }
        }

        // ---- epilogue: running argmax (ascending codes, strict >) ----
        #pragma unroll
        for (int nt = 0; nt < 4; nt++) {
            int loc   = nb * 32 + nt * 8 + 2 * tg;
            int cbase = tile * TNC + loc;
            float y0 = y2s[loc], y1 = y2s[loc + 1];
            float s;
            s = chh[nt][0] + cxx[nt][0] - 0.5f * y0; if (s > rm0) { rm0 = s; ri0 = cbase; }
            s = chh[nt][1] + cxx[nt][1] - 0.5f * y1; if (s > rm0) { rm0 = s; ri0 = cbase + 1; }
            s = chh[nt][2] + cxx[nt][2] - 0.5f * y0; if (s > rm1) { rm1 = s; ri1 = cbase; }
            s = chh[nt][3] + cxx[nt][3] - 0.5f * y1; if (s > rm1) { rm1 = s; ri1 = cbase + 1; }
        }
    }

    // ---- reduce over the 4 tg lanes (xor 1,2 stays inside quad) ----
    #pragma unroll
    for (int o = 1; o <= 2; o <<= 1) {
        float ov; int oi;
        ov = __shfl_xor_sync(0xffffffffu, rm0, o);
        oi = __shfl_xor_sync(0xffffffffu, ri0, o);
        if (ov > rm0 || (ov == rm0 && oi < ri0)) { rm0 = ov; ri0 = oi; }
        ov = __shfl_xor_sync(0xffffffffu, rm1, o);
        oi = __shfl_xor_sync(0xffffffffu, ri1, o);
        if (ov > rm1 || (ov == rm1 && oi < ri1)) { rm1 = ov; ri1 = oi; }
    }
    if (tg == 0) {
        int r = mb * 16 + g;
        sred[nb * 64 + r]     = rm0;  ired[nb * 64 + r]     = ri0;
        sred[nb * 64 + r + 8] = rm1;  ired[nb * 64 + r + 8] = ri1;
    }
    __syncthreads();

    if (t < TMQ) {
        float s0 = sred[t], s1 = sred[64 + t];
        int   i0 = ired[t], i1 = ired[64 + t];
        int id = (s1 > s0 || (s1 == s0 && i1 < i0)) ? i1 : i0;
        inds[t] = id;
        if (out_size >= QSIZE + M * HEADS)
            out[QSIZE + (size_t)(bm * TMQ + t) * HEADS + h] = (float)id;
    }
    __syncthreads();

    // ---- gather quantized codes (layout b n (h d)) ----
    const float* ebase = embed + (size_t)h * CB * D;
    #pragma unroll
    for (int s = 0; s < 4; s++) {
        int slot = t + s * NTHREADS;
        int r = slot >> 4, kq = slot & 15;
        int id = inds[r];
        float4 v = *reinterpret_cast<const float4*>(ebase + (size_t)id * D + kq * 4);
        *reinterpret_cast<float4*>(out + (size_t)(bm * TMQ + r) * DIM + h * D + kq * 4) = v;
    }
}

extern "C" void kernel_launch(void* const* d_in, const int* in_sizes, int n_in,
                              void* d_out, int out_size) {
    const float* x     = (const float*)d_in[0];   // [4,2048,256]
    const float* embed = (const float*)d_in[1];   // [4,8192,64]
    float* out = (float*)d_out;

    cudaFuncSetAttribute(vq_main_kernel,
                         cudaFuncAttributeMaxDynamicSharedMemorySize, SMEM_BYTES);

    vq_y2_kernel<<<(HEADS * CB) / 8, 256>>>(embed);
    vq_xprep_kernel<<<2048, 256>>>(x);
    vq_eprep_kernel<<<4096, 256>>>(embed);

    dim3 grid(M / TMQ, HEADS);
    vq_main_kernel<<<grid, NTHREADS, SMEM_BYTES>>>(embed, out, out_size);
}

// round 13
// speedup vs baseline: 2.3759x; 1.1431x over previous
#include <cuda_runtime.h>
#include <cstdint>

#define HEADS 4
#define CB    8192
#define D     64
#define M     8192            // B*N
#define DIM   256
#define QSIZE (M*DIM)
#define TMQ   64              // queries per block
#define TNC   64              // codes per tile
#define NTILES (CB/TNC)       // 128
#define NTHREADS 256

// fragment-order scratch (module globals; no runtime alloc)
// X: ablock = h*512 + (q/16); [ablock][chunk 8][lane 32][4]  (hi and lo separate)
// B packed: eblock = h*1024 + (c/8); [eblock][chunk 8][lane 32][4] = (hi0,hi1,lo0,lo1)
__device__ float gXhi[2097152];
__device__ float gXlo[2097152];
__device__ float gBpk[4194304];
__device__ float g_y2[HEADS * CB];

// smem layout (bytes): Es[2] 2x32768 | y2[2] 2x256 | sred 512 | ired 512 | inds 256
#define SM_ES0   0
#define SM_ES1   32768
#define SM_Y20   65536
#define SM_Y21   65792
#define SM_SRED  66048
#define SM_IRED  66560
#define SM_INDS  67072
#define SMEM_BYTES 67328

#define CP_ASYNC16(dst_u32, src_ptr) \
    asm volatile("cp.async.cg.shared.global [%0], [%1], 16;" \
                 :: "r"(dst_u32), "l"(src_ptr))
#define CP_COMMIT()  asm volatile("cp.async.commit_group;")
#define CP_WAIT1()   asm volatile("cp.async.wait_group 1;")

// ---------------------------------------------------------------------------
__device__ __forceinline__ uint32_t to_tf32(float f) {
    uint32_t r;
    asm("cvt.rna.tf32.f32 %0, %1;" : "=r"(r) : "f"(f));
    return r;
}

__device__ __forceinline__ void mma_tf32(float c[4], const uint32_t a[4],
                                         uint32_t b0, uint32_t b1) {
    asm volatile(
        "mma.sync.aligned.m16n8k8.row.col.f32.tf32.tf32.f32 "
        "{%0,%1,%2,%3}, {%4,%5,%6,%7}, {%8,%9}, {%0,%1,%2,%3};"
        : "+f"(c[0]), "+f"(c[1]), "+f"(c[2]), "+f"(c[3])
        : "r"(a[0]), "r"(a[1]), "r"(a[2]), "r"(a[3]), "r"(b0), "r"(b1));
}

// ---------------------------------------------------------------------------
__global__ void vq_y2_kernel(const float* __restrict__ embed) {
    int gw   = (blockIdx.x * blockDim.x + threadIdx.x) >> 5;
    int lane = threadIdx.x & 31;
    if (gw >= HEADS * CB) return;
    float2 v = reinterpret_cast<const float2*>(embed + (size_t)gw * D)[lane];
    float s = fmaf(v.x, v.x, v.y * v.y);
    #pragma unroll
    for (int o = 16; o; o >>= 1) s += __shfl_xor_sync(0xffffffffu, s, o);
    if (lane == 0) g_y2[gw] = s;
}

// ---------------------------------------------------------------------------
// X prep: A-fragment order: a0=A[g][tg], a1=A[g+8][tg], a2=A[g][tg+4], a3=A[g+8][tg+4]
// ---------------------------------------------------------------------------
__global__ void vq_xprep_kernel(const float* __restrict__ x) {
    int tid = blockIdx.x * blockDim.x + threadIdx.x;   // < 524288
    int lane = tid & 31, chunk = (tid >> 5) & 7, ab = tid >> 8;
    int h = ab >> 9, mbg = ab & 511;
    int g = lane >> 2, tg = lane & 3;
    size_t base = (size_t)(16 * mbg + g) * DIM + h * D + 8 * chunk;
    float a0 = x[base + tg];
    float a1 = x[base + 8 * DIM + tg];
    float a2 = x[base + tg + 4];
    float a3 = x[base + 8 * DIM + tg + 4];
    float f0 = __uint_as_float(to_tf32(a0)), f1 = __uint_as_float(to_tf32(a1));
    float f2 = __uint_as_float(to_tf32(a2)), f3 = __uint_as_float(to_tf32(a3));
    size_t o = (size_t)tid * 4;
    *reinterpret_cast<float4*>(gXhi + o) = make_float4(f0, f1, f2, f3);
    *reinterpret_cast<float4*>(gXlo + o) = make_float4(
        __uint_as_float(to_tf32(a0 - f0)), __uint_as_float(to_tf32(a1 - f1)),
        __uint_as_float(to_tf32(a2 - f2)), __uint_as_float(to_tf32(a3 - f3)));
}

// ---------------------------------------------------------------------------
// E prep: packed B fragments (hi0, hi1, lo0, lo1) per (eblock, chunk, lane).
// b0 = e[n=g][k=tg], b1 = e[n=g][k=tg+4]
// ---------------------------------------------------------------------------
__global__ void vq_eprep_kernel(const float* __restrict__ embed) {
    int tid = blockIdx.x * blockDim.x + threadIdx.x;   // < 1048576
    int lane = tid & 31, chunk = (tid >> 5) & 7, eb = tid >> 8;
    int h = eb >> 10, nbg = eb & 1023;
    int g = lane >> 2, tg = lane & 3;
    size_t base = ((size_t)h * CB + 8 * nbg + g) * D + 8 * chunk + tg;
    float b0 = embed[base];
    float b1 = embed[base + 4];
    float f0 = __uint_as_float(to_tf32(b0)), f1 = __uint_as_float(to_tf32(b1));
    *reinterpret_cast<float4*>(gBpk + (size_t)tid * 4) = make_float4(
        f0, f1,
        __uint_as_float(to_tf32(b0 - f0)), __uint_as_float(to_tf32(b1 - f1)));
}

// ---------------------------------------------------------------------------
// cp.async fill of one E tile (+y2) into buffer
// ---------------------------------------------------------------------------
__device__ __forceinline__ void fill_tile(int h, int tile, int t,
                                          char* smem, int es_off, int y2_off,
                                          const float* y2b) {
    const float4* ep = reinterpret_cast<const float4*>(gBpk) +
                       (size_t)(h * 1024 + tile * 8) * 256;
    uint32_t dst = (uint32_t)__cvta_generic_to_shared(smem + es_off);
    #pragma unroll
    for (int i = 0; i < 8; i++)
        CP_ASYNC16(dst + (t + i * 256) * 16, ep + t + i * 256);
    if (t < 16) {
        uint32_t yd = (uint32_t)__cvta_generic_to_shared(smem + y2_off) + t * 16;
        CP_ASYNC16(yd, y2b + tile * TNC + t * 4);
    }
}

// ---------------------------------------------------------------------------
// Main: grid (M/64, HEADS), 256 thr = 8 warps (mb = w>>1, nb = w&1).
// A fragments register-resident; E double-buffered via cp.async.
// Per chunk: 4 packed-B LDS.128 -> 12 MMAs (split acc: chh, cxx).
// score(c) = x.e_c - 0.5*|e_c|^2 ; argmax, first-index tie-break.
// ---------------------------------------------------------------------------
__global__ __launch_bounds__(NTHREADS, 2)
void vq_main_kernel(const float* __restrict__ embed,
                    float* __restrict__ out, int out_size) {
    extern __shared__ char smem[];
    float* sred = reinterpret_cast<float*>(smem + SM_SRED);
    int*   ired = reinterpret_cast<int*>(smem + SM_IRED);
    int*   inds = reinterpret_cast<int*>(smem + SM_INDS);

    const int h = blockIdx.y, bm = blockIdx.x;
    const int t = threadIdx.x, lane = t & 31, w = t >> 5;
    const int mb = w >> 1, nb = w & 1;
    const int g = lane >> 2, tg = lane & 3;

    const float* y2b = g_y2 + h * CB;

    // ---- prologue: async-fill tile 0 into buffer 0 ----
    fill_tile(h, 0, t, smem, SM_ES0, SM_Y20, y2b);
    CP_COMMIT();

    // ---- A fragments -> registers (once). ablock = h*512 + bm*4 + mb ----
    uint32_t Ah[8][4], Al[8][4];
    {
        const float4* xh = reinterpret_cast<const float4*>(gXhi) +
                           (size_t)(h * 512 + bm * 4 + mb) * 256;
        const float4* xl = reinterpret_cast<const float4*>(gXlo) +
                           (size_t)(h * 512 + bm * 4 + mb) * 256;
        #pragma unroll
        for (int c = 0; c < 8; c++) {
            float4 vh = xh[c * 32 + lane];
            float4 vl = xl[c * 32 + lane];
            Ah[c][0] = __float_as_uint(vh.x); Ah[c][1] = __float_as_uint(vh.y);
            Ah[c][2] = __float_as_uint(vh.z); Ah[c][3] = __float_as_uint(vh.w);
            Al[c][0] = __float_as_uint(vl.x); Al[c][1] = __float_as_uint(vl.y);
            Al[c][2] = __float_as_uint(vl.z); Al[c][3] = __float_as_uint(vl.w);
        }
    }

    float rm0 = -3.4e38f, rm1 = -3.4e38f;
    int   ri0 = 0,        ri1 = 0;

    for (int tile = 0; tile < NTILES; tile++) {
        const int p = tile & 1;
        __syncthreads();     // everyone done READING buffer p^1 (prev compute)
        if (tile + 1 < NTILES)
            fill_tile(h, tile + 1, t, smem,
                      p ? SM_ES0 : SM_ES1, p ? SM_Y20 : SM_Y21, y2b);
        CP_COMMIT();
        CP_WAIT1();          // fill(tile) complete (was in flight during prev compute)
        __syncthreads();     // make it visible to all warps

        const float4* EsF4 = reinterpret_cast<const float4*>(
            smem + (p ? SM_ES1 : SM_ES0));
        const float* y2s = reinterpret_cast<const float*>(
            smem + (p ? SM_Y21 : SM_Y20));

        float chh[4][4], cxx[4][4];
        #pragma unroll
        for (int nt = 0; nt < 4; nt++)
            #pragma unroll
            for (int j = 0; j < 4; j++) { chh[nt][j] = 0.0f; cxx[nt][j] = 0.0f; }

        #pragma unroll
        for (int chunk = 0; chunk < 8; chunk++) {
            #pragma unroll
            for (int nt = 0; nt < 4; nt++) {
                int nblk = nb * 4 + nt;
                float4 bp = EsF4[(nblk * 8 + chunk) * 32 + lane];
                uint32_t bh0 = __float_as_uint(bp.x), bh1 = __float_as_uint(bp.y);
                uint32_t bl0 = __float_as_uint(bp.z), bl1 = __float_as_uint(bp.w);
                mma_tf32(chh[nt], Ah[chunk], bh0, bh1);   // hi*hi
                mma_tf32(cxx[nt], Ah[chunk], bl0, bl1);   // hi*lo
                mma_tf32(cxx[nt], Al[chunk], bh0, bh1);   // lo*hi
            }
        }

        // ---- epilogue: running argmax (ascending codes, strict >) ----
        #pragma unroll
        for (int nt = 0; nt < 4; nt++) {
            int loc   = nb * 32 + nt * 8 + 2 * tg;
            int cbase = tile * TNC + loc;
            float y0 = y2s[loc], y1 = y2s[loc + 1];
            float s;
            s = chh[nt][0] + cxx[nt][0] - 0.5f * y0; if (s > rm0) { rm0 = s; ri0 = cbase; }
            s = chh[nt][1] + cxx[nt][1] - 0.5f * y1; if (s > rm0) { rm0 = s; ri0 = cbase + 1; }
            s = chh[nt][2] + cxx[nt][2] - 0.5f * y0; if (s > rm1) { rm1 = s; ri1 = cbase; }
            s = chh[nt][3] + cxx[nt][3] - 0.5f * y1; if (s > rm1) { rm1 = s; ri1 = cbase + 1; }
        }
    }

    // ---- reduce over the 4 tg lanes (xor 1,2 stays inside quad) ----
    #pragma unroll
    for (int o = 1; o <= 2; o <<= 1) {
        float ov; int oi;
        ov = __shfl_xor_sync(0xffffffffu, rm0, o);
        oi = __shfl_xor_sync(0xffffffffu, ri0, o);
        if (ov > rm0 || (ov == rm0 && oi < ri0)) { rm0 = ov; ri0 = oi; }
        ov = __shfl_xor_sync(0xffffffffu, rm1, o);
        oi = __shfl_xor_sync(0xffffffffu, ri1, o);
        if (ov > rm1 || (ov == rm1 && oi < ri1)) { rm1 = ov; ri1 = oi; }
    }
    if (tg == 0) {
        int r = mb * 16 + g;
        sred[nb * 64 + r]     = rm0;  ired[nb * 64 + r]     = ri0;
        sred[nb * 64 + r + 8] = rm1;  ired[nb * 64 + r + 8] = ri1;
    }
    __syncthreads();

    if (t < TMQ) {
        float s0 = sred[t], s1 = sred[64 + t];
        int   i0 = ired[t], i1 = ired[64 + t];
        int id = (s1 > s0 || (s1 == s0 && i1 < i0)) ? i1 : i0;
        inds[t] = id;
        if (out_size >= QSIZE + M * HEADS)
            out[QSIZE + (size_t)(bm * TMQ + t) * HEADS + h] = (float)id;
    }
    __syncthreads();

    // ---- gather quantized codes (layout b n (h d)) ----
    const float* ebase = embed + (size_t)h * CB * D;
    #pragma unroll
    for (int s = 0; s < 4; s++) {
        int slot = t + s * NTHREADS;
        int r = slot >> 4, kq = slot & 15;
        int id = inds[r];
        float4 v = *reinterpret_cast<const float4*>(ebase + (size_t)id * D + kq * 4);
        *reinterpret_cast<float4*>(out + (size_t)(bm * TMQ + r) * DIM + h * D + kq * 4) = v;
    }
}

extern "C" void kernel_launch(void* const* d_in, const int* in_sizes, int n_in,
                              void* d_out, int out_size) {
    const float* x     = (const float*)d_in[0];   // [4,2048,256]
    const float* embed = (const float*)d_in[1];   // [4,8192,64]
    float* out = (float*)d_out;

    cudaFuncSetAttribute(vq_main_kernel,
                         cudaFuncAttributeMaxDynamicSharedMemorySize, SMEM_BYTES);

    vq_y2_kernel<<<(HEADS * CB) / 8, 256>>>(embed);
    vq_xprep_kernel<<<2048, 256>>>(x);
    vq_eprep_kernel<<<4096, 256>>>(embed);

    dim3 grid(M / TMQ, HEADS);
    vq_main_kernel<<<grid, NTHREADS, SMEM_BYTES>>>(embed, out, out_size);
}